// round 12
// baseline (speedup 1.0000x reference)
#include <cuda_runtime.h>
#include <cuda_bf16.h>
#include <math.h>

#define C 32
#define CM_SIZE (C * C)
#define NT 1024  // threads per block

// Scratch confusion-matrix accumulator. Invariant: zero at kernel_launch entry.
// hist_kernel accumulates; finalize_kernel reads it and resets it to zero.
__device__ float g_hist[CM_SIZE];

// Map float bits to unsigned such that unsigned order == float order.
__device__ __forceinline__ unsigned sortable(float f) {
    int b = __float_as_int(f);
    return (unsigned)(b ^ ((b >> 31) | 0x80000000));
}

// Lane-local argmax over 4 elements (strict > keeps first occurrence),
// packed as key = (sortable_value & ~31) | (31 - idx) so that unsigned max
// picks the larger value, and the SMALLER index on (truncated) ties.
__device__ __forceinline__ unsigned local_key(float4 v, int base) {
    float best = v.x; int bi = base;
    bool c;
    c = v.y > best; best = c ? v.y : best; bi = c ? base + 1 : bi;
    c = v.z > best; best = c ? v.z : best; bi = c ? base + 2 : bi;
    c = v.w > best; best = c ? v.w : best; bi = c ? base + 3 : bi;
    return (sortable(best) & ~31u) | (unsigned)(31 - bi);
}

// Butterfly max over the 8 lanes sharing (lane >> 3); returns argmax index.
__device__ __forceinline__ int reduce8_idx(unsigned key) {
#pragma unroll
    for (int o = 1; o < 8; o <<= 1) {
        unsigned ok = __shfl_xor_sync(0xffffffffu, key, o);
        key = key > ok ? key : ok;
    }
    return 31 - (int)(key & 31u);
}

__global__ void __launch_bounds__(NT, 2) hist_kernel(
    const float* __restrict__ yt,
    const float* __restrict__ yp,
    int n_rows)
{
    __shared__ int sh[CM_SIZE];
    for (int i = threadIdx.x; i < CM_SIZE; i += NT) sh[i] = 0;
    __syncthreads();

    const int lane = threadIdx.x & 31;
    const int gw   = (blockIdx.x * NT + threadIdx.x) >> 5;    // global warp id
    const int nw   = (gridDim.x * NT) >> 5;                   // total warps
    const int base = (lane & 7) * 4;   // element offset within row
    const bool is_head = (lane & 7) == 0;

    // 8 rows per warp-iteration: 4 fully-coalesced 512B LDG.128 sweeps.
    const int ngroups = n_rows >> 3;
    for (int g = gw; g < ngroups; g += nw) {
        const float4* at = (const float4*)(yt + (size_t)g * 8 * C);
        const float4* ap = (const float4*)(yp + (size_t)g * 8 * C);
        float4 t0 = at[lane];
        float4 p0 = ap[lane];
        float4 t1 = at[lane + 32];
        float4 p1 = ap[lane + 32];

        unsigned kt0 = local_key(t0, base);
        unsigned kp0 = local_key(p0, base);
        unsigned kt1 = local_key(t1, base);
        unsigned kp1 = local_key(p1, base);

        int ti0 = reduce8_idx(kt0);
        int pi0 = reduce8_idx(kp0);
        int ti1 = reduce8_idx(kt1);
        int pi1 = reduce8_idx(kp1);

        if (is_head) {   // lanes 0,8,16,24 each hold one row's result
            atomicAdd(&sh[ti0 * C + pi0], 1);
            atomicAdd(&sh[ti1 * C + pi1], 1);
        }
    }

    // Tail (n_rows % 8 rows): scalar, handled by global warp 0.
    if (gw == 0) {
        int tail = n_rows & 7;
        if (lane < tail) {
            size_t r = (size_t)(n_rows & ~7) + lane;
            const float* a = yt + r * C;
            const float* b = yp + r * C;
            float bt = a[0]; int ti = 0;
            float bp = b[0]; int pi = 0;
#pragma unroll
            for (int k = 1; k < C; k++) {
                if (a[k] > bt) { bt = a[k]; ti = k; }
                if (b[k] > bp) { bp = b[k]; pi = k; }
            }
            atomicAdd(&sh[ti * C + pi], 1);
        }
    }

    __syncthreads();
    // Staggered flush: block b starts at a different histogram offset so
    // concurrent blocks hit different addresses / LTS slices instead of
    // convoying per-address at the L2 atomic ALU.
    {
        int off = (blockIdx.x * 131) & (CM_SIZE - 1);
        for (int i = threadIdx.x; i < CM_SIZE; i += NT) {
            int idx = (i + off) & (CM_SIZE - 1);
            int v = sh[idx];
            if (v) atomicAdd(&g_hist[idx], (float)v);
        }
    }
}

// Parallel finalize: 1024 threads, ONE (g_hist, cm_in) load pair per thread so
// all 2048 loads are in flight concurrently (one memory-latency total instead
// of a 32-deep serialized chain per thread).
__global__ void finalize_kernel(const float* __restrict__ cm_in, float* __restrict__ out) {
    __shared__ float colsum[C];
    __shared__ float diag[C];

    int tid = threadIdx.x;         // tid = i*C + j
    int j = tid & (C - 1);         // column
    int i = tid >> 5;              // row

    float v = g_hist[tid] + cm_in[tid];
    // Reset scratch for the next graph replay: each element is read only by
    // its owning thread, and that read (into v) precedes this store.
    g_hist[tid] = 0.0f;

    if (tid < C) colsum[tid] = 0.0f;
    __syncthreads();

    // Lanes within a warp hit 32 distinct addresses -> conflict-free ATOMS.
    atomicAdd(&colsum[j], v);
    if (i == j) diag[j] = v;
    __syncthreads();

    if (tid < C) {
        const float EPS = 1.1920928955078125e-07f;  // FLT_EPSILON
        float prec = diag[tid] / (colsum[tid] + EPS);
#pragma unroll
        for (int o = 16; o > 0; o >>= 1)
            prec += __shfl_xor_sync(0xffffffffu, prec, o);
        if (tid == 0) out[0] = prec * (1.0f / C);
    }
}

extern "C" void kernel_launch(void* const* d_in, const int* in_sizes, int n_in,
                              void* d_out, int out_size) {
    const float* y_true = (const float*)d_in[0];
    const float* y_pred = (const float*)d_in[1];
    const float* cm_in  = (const float*)d_in[2];
    float* out = (float*)d_out;

    int n_rows = in_sizes[0] / C;

    // 152 SMs * 2 blocks of 1024 threads — the proven R9 mainloop.
    hist_kernel<<<152 * 2, NT>>>(y_true, y_pred, n_rows);
    finalize_kernel<<<1, CM_SIZE>>>(cm_in, out);
}

// round 13
// speedup vs baseline: 1.0515x; 1.0515x over previous
#include <cuda_runtime.h>
#include <cuda_bf16.h>
#include <math.h>

#define C 32
#define CM_SIZE (C * C)
#define NT 1024  // threads per block

// Scratch confusion-matrix accumulator. Invariant: zero at kernel_launch entry.
// hist_kernel accumulates; finalize_kernel reads it and resets it to zero.
__device__ float g_hist[CM_SIZE];

// Map float bits to unsigned such that unsigned order == float order.
__device__ __forceinline__ unsigned sortable(float f) {
    int b = __float_as_int(f);
    return (unsigned)(b ^ ((b >> 31) | 0x80000000));
}

// Lane-local argmax over 4 elements (strict > keeps first occurrence),
// packed as key = (sortable_value & ~31) | (31 - idx) so that unsigned max
// picks the larger value, and the SMALLER index on (truncated) ties.
__device__ __forceinline__ unsigned local_key(float4 v, int base) {
    float best = v.x; int bi = base;
    bool c;
    c = v.y > best; best = c ? v.y : best; bi = c ? base + 1 : bi;
    c = v.z > best; best = c ? v.z : best; bi = c ? base + 2 : bi;
    c = v.w > best; best = c ? v.w : best; bi = c ? base + 3 : bi;
    return (sortable(best) & ~31u) | (unsigned)(31 - bi);
}

// Butterfly max over the 8 lanes sharing (lane >> 3); returns argmax index.
__device__ __forceinline__ int reduce8_idx(unsigned key) {
#pragma unroll
    for (int o = 1; o < 8; o <<= 1) {
        unsigned ok = __shfl_xor_sync(0xffffffffu, key, o);
        key = key > ok ? key : ok;
    }
    return 31 - (int)(key & 31u);
}

__global__ void __launch_bounds__(NT, 2) hist_kernel(
    const float* __restrict__ yt,
    const float* __restrict__ yp,
    int n_rows)
{
    __shared__ int sh[CM_SIZE];
    for (int i = threadIdx.x; i < CM_SIZE; i += NT) sh[i] = 0;
    __syncthreads();

    const int lane = threadIdx.x & 31;
    const int gw   = (blockIdx.x * NT + threadIdx.x) >> 5;    // global warp id
    const int nw   = (gridDim.x * NT) >> 5;                   // total warps
    const int base = (lane & 7) * 4;   // element offset within row
    const bool is_head = (lane & 7) == 0;

    // 8 rows per warp-iteration: 4 fully-coalesced 512B LDG.128 sweeps.
    const int ngroups = n_rows >> 3;
    for (int g = gw; g < ngroups; g += nw) {
        const float4* at = (const float4*)(yt + (size_t)g * 8 * C);
        const float4* ap = (const float4*)(yp + (size_t)g * 8 * C);
        float4 t0 = at[lane];
        float4 p0 = ap[lane];
        float4 t1 = at[lane + 32];
        float4 p1 = ap[lane + 32];

        unsigned kt0 = local_key(t0, base);
        unsigned kp0 = local_key(p0, base);
        unsigned kt1 = local_key(t1, base);
        unsigned kp1 = local_key(p1, base);

        int ti0 = reduce8_idx(kt0);
        int pi0 = reduce8_idx(kp0);
        int ti1 = reduce8_idx(kt1);
        int pi1 = reduce8_idx(kp1);

        if (is_head) {   // lanes 0,8,16,24 each hold one row's result
            atomicAdd(&sh[ti0 * C + pi0], 1);
            atomicAdd(&sh[ti1 * C + pi1], 1);
        }
    }

    // Tail (n_rows % 8 rows): scalar, handled by global warp 0.
    if (gw == 0) {
        int tail = n_rows & 7;
        if (lane < tail) {
            size_t r = (size_t)(n_rows & ~7) + lane;
            const float* a = yt + r * C;
            const float* b = yp + r * C;
            float bt = a[0]; int ti = 0;
            float bp = b[0]; int pi = 0;
#pragma unroll
            for (int k = 1; k < C; k++) {
                if (a[k] > bt) { bt = a[k]; ti = k; }
                if (b[k] > bp) { bp = b[k]; pi = k; }
            }
            atomicAdd(&sh[ti * C + pi], 1);
        }
    }

    __syncthreads();
    // Staggered flush: block b starts at a different histogram offset so
    // concurrent blocks hit different addresses / LTS slices instead of
    // convoying per-address at the L2 atomic ALU.
    {
        int off = (blockIdx.x * 131) & (CM_SIZE - 1);
        for (int i = threadIdx.x; i < CM_SIZE; i += NT) {
            int idx = (i + off) & (CM_SIZE - 1);
            int v = sh[idx];
            if (v) atomicAdd(&g_hist[idx], (float)v);
        }
    }
}

__global__ void finalize_kernel(const float* __restrict__ cm_in, float* __restrict__ out) {
    int j = threadIdx.x;  // column index, single warp
    float colsum = 0.0f;
    float tp = 0.0f;
#pragma unroll
    for (int i = 0; i < C; i++) {
        float v = g_hist[i * C + j] + cm_in[i * C + j];
        colsum += v;
        if (i == j) tp = v;
    }
    const float EPS = 1.1920928955078125e-07f;  // FLT_EPSILON
    float prec = tp / (colsum + EPS);
#pragma unroll
    for (int o = 16; o > 0; o >>= 1)
        prec += __shfl_xor_sync(0xffffffffu, prec, o);
    if (j == 0) out[0] = prec * (1.0f / C);
    __syncwarp();
    // Reset scratch for the next graph replay. Safe: every lane's loads were
    // consumed by the shfl reduction above, which precedes these stores in
    // warp-synchronous program order.
#pragma unroll
    for (int k = 0; k < C; k++) g_hist[j * C + k] = 0.0f;
}

extern "C" void kernel_launch(void* const* d_in, const int* in_sizes, int n_in,
                              void* d_out, int out_size) {
    const float* y_true = (const float*)d_in[0];
    const float* y_pred = (const float*)d_in[1];
    const float* cm_in  = (const float*)d_in[2];
    float* out = (float*)d_out;

    int n_rows = in_sizes[0] / C;

    // 152 SMs * 2 blocks of 1024 threads: minimal block count (minimal
    // end-of-kernel atomic drain) at full 2048 threads/SM occupancy.
    hist_kernel<<<152 * 2, NT>>>(y_true, y_pred, n_rows);
    finalize_kernel<<<1, C>>>(cm_in, out);
}

// round 14
// speedup vs baseline: 1.0804x; 1.0274x over previous
#include <cuda_runtime.h>
#include <cuda_bf16.h>
#include <math.h>

#define C 32
#define CM_SIZE (C * C)
#define NT 1024  // threads per block

// Scratch confusion-matrix accumulator. Invariant: zero at kernel_launch entry.
// hist_kernel accumulates; finalize_kernel reads it and resets it to zero.
__device__ float g_hist[CM_SIZE];

// Map float bits to unsigned such that unsigned order == float order.
__device__ __forceinline__ unsigned sortable(float f) {
    int b = __float_as_int(f);
    return (unsigned)(b ^ ((b >> 31) | 0x80000000));
}

// Lane-local argmax over 4 elements (strict > keeps first occurrence),
// packed as key = (sortable_value & ~31) | (31 - idx) so that unsigned max
// picks the larger value, and the SMALLER index on (truncated) ties.
__device__ __forceinline__ unsigned local_key(float4 v, int base) {
    float best = v.x; int bi = base;
    bool c;
    c = v.y > best; best = c ? v.y : best; bi = c ? base + 1 : bi;
    c = v.z > best; best = c ? v.z : best; bi = c ? base + 2 : bi;
    c = v.w > best; best = c ? v.w : best; bi = c ? base + 3 : bi;
    return (sortable(best) & ~31u) | (unsigned)(31 - bi);
}

// Butterfly max over the 8 lanes sharing (lane >> 3); returns argmax index.
__device__ __forceinline__ int reduce8_idx(unsigned key) {
#pragma unroll
    for (int o = 1; o < 8; o <<= 1) {
        unsigned ok = __shfl_xor_sync(0xffffffffu, key, o);
        key = key > ok ? key : ok;
    }
    return 31 - (int)(key & 31u);
}

__global__ void __launch_bounds__(NT, 2) hist_kernel(
    const float* __restrict__ yt,
    const float* __restrict__ yp,
    int n_rows)
{
    __shared__ int sh[CM_SIZE];
    for (int i = threadIdx.x; i < CM_SIZE; i += NT) sh[i] = 0;
    __syncthreads();

    const int lane = threadIdx.x & 31;
    const int gw   = (blockIdx.x * NT + threadIdx.x) >> 5;    // global warp id
    const int nw   = (gridDim.x * NT) >> 5;                   // total warps
    const int base = (lane & 7) * 4;   // element offset within row
    const bool is_head = (lane & 7) == 0;

    // 8 rows per warp-iteration: 4 fully-coalesced 512B LDG.128 sweeps.
    // Streaming (.cs, evict-first) — data is touched exactly once, so avoid
    // L2 fill/victim churn on the pure-streaming path.
    const int ngroups = n_rows >> 3;
    for (int g = gw; g < ngroups; g += nw) {
        const float4* at = (const float4*)(yt + (size_t)g * 8 * C);
        const float4* ap = (const float4*)(yp + (size_t)g * 8 * C);
        float4 t0 = __ldcs(at + lane);
        float4 p0 = __ldcs(ap + lane);
        float4 t1 = __ldcs(at + lane + 32);
        float4 p1 = __ldcs(ap + lane + 32);

        unsigned kt0 = local_key(t0, base);
        unsigned kp0 = local_key(p0, base);
        unsigned kt1 = local_key(t1, base);
        unsigned kp1 = local_key(p1, base);

        int ti0 = reduce8_idx(kt0);
        int pi0 = reduce8_idx(kp0);
        int ti1 = reduce8_idx(kt1);
        int pi1 = reduce8_idx(kp1);

        if (is_head) {   // lanes 0,8,16,24 each hold one row's result
            atomicAdd(&sh[ti0 * C + pi0], 1);
            atomicAdd(&sh[ti1 * C + pi1], 1);
        }
    }

    // Tail (n_rows % 8 rows): scalar, handled by global warp 0.
    if (gw == 0) {
        int tail = n_rows & 7;
        if (lane < tail) {
            size_t r = (size_t)(n_rows & ~7) + lane;
            const float* a = yt + r * C;
            const float* b = yp + r * C;
            float bt = a[0]; int ti = 0;
            float bp = b[0]; int pi = 0;
#pragma unroll
            for (int k = 1; k < C; k++) {
                if (a[k] > bt) { bt = a[k]; ti = k; }
                if (b[k] > bp) { bp = b[k]; pi = k; }
            }
            atomicAdd(&sh[ti * C + pi], 1);
        }
    }

    __syncthreads();
    // Staggered flush: block b starts at a different histogram offset so
    // concurrent blocks hit different addresses / LTS slices instead of
    // convoying per-address at the L2 atomic ALU.
    {
        int off = (blockIdx.x * 131) & (CM_SIZE - 1);
        for (int i = threadIdx.x; i < CM_SIZE; i += NT) {
            int idx = (i + off) & (CM_SIZE - 1);
            int v = sh[idx];
            if (v) atomicAdd(&g_hist[idx], (float)v);
        }
    }
}

__global__ void finalize_kernel(const float* __restrict__ cm_in, float* __restrict__ out) {
    int j = threadIdx.x;  // column index, single warp
    float colsum = 0.0f;
    float tp = 0.0f;
#pragma unroll
    for (int i = 0; i < C; i++) {
        float v = g_hist[i * C + j] + cm_in[i * C + j];
        colsum += v;
        if (i == j) tp = v;
    }
    const float EPS = 1.1920928955078125e-07f;  // FLT_EPSILON
    float prec = tp / (colsum + EPS);
#pragma unroll
    for (int o = 16; o > 0; o >>= 1)
        prec += __shfl_xor_sync(0xffffffffu, prec, o);
    if (j == 0) out[0] = prec * (1.0f / C);
    __syncwarp();
    // Reset scratch for the next graph replay. Safe: every lane's loads were
    // consumed by the shfl reduction above, which precedes these stores in
    // warp-synchronous program order.
#pragma unroll
    for (int k = 0; k < C; k++) g_hist[j * C + k] = 0.0f;
}

extern "C" void kernel_launch(void* const* d_in, const int* in_sizes, int n_in,
                              void* d_out, int out_size) {
    const float* y_true = (const float*)d_in[0];
    const float* y_pred = (const float*)d_in[1];
    const float* cm_in  = (const float*)d_in[2];
    float* out = (float*)d_out;

    int n_rows = in_sizes[0] / C;

    // 152 SMs * 2 blocks of 1024 threads: minimal block count (minimal
    // end-of-kernel atomic drain) at full 2048 threads/SM occupancy.
    hist_kernel<<<152 * 2, NT>>>(y_true, y_pred, n_rows);
    finalize_kernel<<<1, C>>>(cm_in, out);
}